// round 16
// baseline (speedup 1.0000x reference)
#include <cuda_runtime.h>
#include <cuda_bf16.h>
#include <math.h>

// Problem constants
#define NB 4          // batch
#define SS 2048       // seq len
#define HID 1024
#define NH 16         // heads
#define NKV 4
#define DD 64
#define NA 2          // two attentions
#define NTOT 2592     // 1024(Q1)+1024(Q2)+256(K1)+256(K2)+16(U1)+16(U2)
#define KPAD 136      // K-tile smem row pad (bank = 8*tig+gid -> conflict-free)

typedef unsigned long long ull;

// ---------------- scratch (device globals; no allocation allowed) ------------
__device__ float g_Bcat[HID * NTOT];        // concatenated weights [K][NTOT]
__device__ float g_C   [NB * SS * NTOT];    // fused projection output  ~85 MB
__device__ float g_UT  [NA * NB * NH * SS]; // scalar-values transposed (a,b,h,s)
__device__ float g_SH  [NA * NB * NH * SS]; // per-head scalar attention out
__device__ float g_SIG [NA * NB * SS];      // sigmoid(score) per attn
__device__ int   g_sizes[NB];

// ---------------- f32x2 packed helpers ---------------------------------------
__device__ __forceinline__ ull pk(float lo, float hi) {
    ull r; asm("mov.b64 %0, {%1, %2};" : "=l"(r) : "f"(lo), "f"(hi)); return r;
}
__device__ __forceinline__ float2 upk(ull v) {
    float2 r; asm("mov.b64 {%0, %1}, %2;" : "=f"(r.x), "=f"(r.y) : "l"(v)); return r;
}
__device__ __forceinline__ void upki(ull v, int& a, int& b) {
    asm("mov.b64 {%0, %1}, %2;" : "=r"(a), "=r"(b) : "l"(v));
}
__device__ __forceinline__ ull pki(int lo, int hi) {
    ull r; asm("mov.b64 %0, {%1, %2};" : "=l"(r) : "r"(lo), "r"(hi)); return r;
}
#define FMA2(d, a, b, c) asm("fma.rn.f32x2 %0, %1, %2, %3;" : "=l"(d) : "l"(a), "l"(b), "l"(c))
#define MUL2(d, a, b)    asm("mul.rn.f32x2 %0, %1, %2;"     : "=l"(d) : "l"(a), "l"(b))
#define ADD2(d, a, b)    asm("add.rn.f32x2 %0, %1, %2;"     : "=l"(d) : "l"(a), "l"(b))

// packed exp (degree-5 2^f poly, exponent splice; valid for |s| < ~80)
__device__ __forceinline__ ull pexp(ull s2) {
    const ull C_L2E  = pk(1.4426950408889634f, 1.4426950408889634f);
    const ull C_MAG  = pk(12582912.0f, 12582912.0f);
    const ull C_NMAG = pk(-12582912.0f, -12582912.0f);
    const ull C_N1   = pk(-1.0f, -1.0f);
    const ull P5 = pk(1.3333558e-3f, 1.3333558e-3f);
    const ull P4 = pk(9.6181291e-3f, 9.6181291e-3f);
    const ull P3 = pk(5.5504109e-2f, 5.5504109e-2f);
    const ull P2 = pk(2.4022651e-1f, 2.4022651e-1f);
    const ull P1 = pk(6.9314718e-1f, 6.9314718e-1f);
    const ull P0 = pk(1.0f, 1.0f);
    ull y2; MUL2(y2, s2, C_L2E);
    ull t2; ADD2(t2, y2, C_MAG);
    ull n2; ADD2(n2, t2, C_NMAG);
    ull fr2; FMA2(fr2, n2, C_N1, y2);
    ull p2 = P5;
    FMA2(p2, p2, fr2, P4);
    FMA2(p2, p2, fr2, P3);
    FMA2(p2, p2, fr2, P2);
    FMA2(p2, p2, fr2, P1);
    FMA2(p2, p2, fr2, P0);
    int t0, t1; upki(t2, t0, t1);
    unsigned e0 = ((unsigned)t0 + 0xB4C0007Fu) << 23;   // (n+127)<<23
    unsigned e1 = ((unsigned)t1 + 0xB4C0007Fu) << 23;
    ull sc2 = pki((int)e0, (int)e1);
    ull r2; MUL2(r2, p2, sc2);
    return r2;
}

// tf32 convert (round-to-nearest-even on 10-bit mantissa, result in b32 reg)
__device__ __forceinline__ unsigned tf32c(float f) {
    unsigned r; asm("cvt.rna.tf32.f32 %0, %1;" : "=r"(r) : "f"(f)); return r;
}

// m16n8k8 tf32 mma, D = A*B + D
__device__ __forceinline__ void mma_tf32(float& c0, float& c1, float& c2, float& c3,
                                         unsigned a0, unsigned a1, unsigned a2, unsigned a3,
                                         unsigned b0, unsigned b1) {
    asm("mma.sync.aligned.m16n8k8.row.col.f32.tf32.tf32.f32 "
        "{%0,%1,%2,%3}, {%4,%5,%6,%7}, {%8,%9}, {%0,%1,%2,%3};"
        : "+f"(c0), "+f"(c1), "+f"(c2), "+f"(c3)
        : "r"(a0), "r"(a1), "r"(a2), "r"(a3), "r"(b0), "r"(b1));
}

// ---------------- weight packing: Bcat[k][c] ---------------------------------
__global__ void pack_weights(const float* __restrict__ Wq1, const float* __restrict__ Wk1,
                             const float* __restrict__ Wv1, const float* __restrict__ Wo1,
                             const float* __restrict__ Wq2, const float* __restrict__ Wk2,
                             const float* __restrict__ Wv2, const float* __restrict__ Wo2) {
    int c = blockIdx.x * 256 + threadIdx.x;
    int k = blockIdx.y;
    if (c >= NTOT) return;
    float v;
    if (c < 1024)      v = Wq1[(size_t)k * 1024 + c];
    else if (c < 2048) v = Wq2[(size_t)k * 1024 + (c - 1024)];
    else if (c < 2304) v = Wk1[(size_t)k * 256 + (c - 2048)];
    else if (c < 2560) v = Wk2[(size_t)k * 256 + (c - 2304)];
    else {
        int cc = c - 2560; int a = cc >> 4, h = cc & 15;
        const float* Wv = a ? Wv2 : Wv1;
        const float* Wo = a ? Wo2 : Wo1;
        int kv = h >> 2;
        float s = 0.f;
        const float* vr = Wv + (size_t)k * (NKV * DD) + kv * DD;
        const float* wr = Wo + h * DD;
#pragma unroll
        for (int d = 0; d < DD; d++) s = fmaf(vr[d], wr[d], s);
        v = s;
    }
    g_Bcat[(size_t)k * NTOT + c] = v;
}

// ---------------- fused projection GEMM: C = x @ Bcat --------------------------
// 128x128 tile, 8-k slabs, double-buffered smem (1 barrier per slab),
// conflict-free load/store mappings, f32x2 microkernel.
// Epilogue also scatters the U columns (2560..2591) into g_UT (transposed).
__global__ __launch_bounds__(256, 2) void gemm_fused(const float* __restrict__ A) {
    __shared__ __align__(16) float As[2][8][128];
    __shared__ __align__(16) float Bs[2][8][128];
    const int N = NTOT, K = HID;
    int tid = threadIdx.x;
    int bm = blockIdx.y * 128;
    int bn = blockIdx.x * 128;
    int ty = tid >> 4, tx = tid & 15;

    int arow = tid >> 1, acol = (tid & 1) * 4;
    int brow = tid >> 5, bcol = (tid & 31) * 4;
    int gn = bn + bcol;
    bool edge = (bn + 128 > N);

    ull acc2[8][4];
#pragma unroll
    for (int i = 0; i < 8; i++)
#pragma unroll
        for (int j = 0; j < 4; j++) acc2[i][j] = 0ull;

    const float* Aptr = A + (size_t)(bm + arow) * K + acol;
    const float* Bptr = g_Bcat + (size_t)brow * N + gn;

    float4 apre, bpre;
    apre = *(const float4*)(Aptr);
    if (!edge) bpre = *(const float4*)(Bptr);
    else {
        bpre.x = (gn + 0 < N) ? Bptr[0] : 0.f;
        bpre.y = (gn + 1 < N) ? Bptr[1] : 0.f;
        bpre.z = (gn + 2 < N) ? Bptr[2] : 0.f;
        bpre.w = (gn + 3 < N) ? Bptr[3] : 0.f;
    }
    As[0][acol + 0][arow] = apre.x;
    As[0][acol + 1][arow] = apre.y;
    As[0][acol + 2][arow] = apre.z;
    As[0][acol + 3][arow] = apre.w;
    *(float4*)&Bs[0][brow][bcol] = bpre;
    __syncthreads();

    for (int k0 = 0; k0 < K; k0 += 8) {
        int buf = (k0 >> 3) & 1;
        bool more = (k0 + 8 < K);

        if (more) {
            apre = *(const float4*)(Aptr + k0 + 8);
            const float* Bp = Bptr + (size_t)(k0 + 8) * N;
            if (!edge) bpre = *(const float4*)Bp;
            else {
                bpre.x = (gn + 0 < N) ? Bp[0] : 0.f;
                bpre.y = (gn + 1 < N) ? Bp[1] : 0.f;
                bpre.z = (gn + 2 < N) ? Bp[2] : 0.f;
                bpre.w = (gn + 3 < N) ? Bp[3] : 0.f;
            }
        }

#pragma unroll
        for (int kk = 0; kk < 8; kk++) {
            float4 a0 = *(const float4*)&As[buf][kk][ty * 4];
            float4 a1 = *(const float4*)&As[buf][kk][64 + ty * 4];
            ulonglong2 b0 = *(const ulonglong2*)&Bs[buf][kk][tx * 4];
            ulonglong2 b1 = *(const ulonglong2*)&Bs[buf][kk][64 + tx * 4];
            ull ap[8];
            ap[0] = pk(a0.x, a0.x); ap[1] = pk(a0.y, a0.y);
            ap[2] = pk(a0.z, a0.z); ap[3] = pk(a0.w, a0.w);
            ap[4] = pk(a1.x, a1.x); ap[5] = pk(a1.y, a1.y);
            ap[6] = pk(a1.z, a1.z); ap[7] = pk(a1.w, a1.w);
            ull bp[4] = {b0.x, b0.y, b1.x, b1.y};
#pragma unroll
            for (int i = 0; i < 8; i++)
#pragma unroll
                for (int j = 0; j < 4; j++) FMA2(acc2[i][j], ap[i], bp[j], acc2[i][j]);
        }

        if (more) {
            int nb = buf ^ 1;
            As[nb][acol + 0][arow] = apre.x;
            As[nb][acol + 1][arow] = apre.y;
            As[nb][acol + 2][arow] = apre.z;
            As[nb][acol + 3][arow] = apre.w;
            *(float4*)&Bs[nb][brow][bcol] = bpre;
            __syncthreads();
        }
    }

#pragma unroll
    for (int i = 0; i < 8; i++) {
        int row = bm + ((i < 4) ? (ty * 4 + i) : (64 + ty * 4 + i - 4));
#pragma unroll
        for (int j = 0; j < 4; j++) {
            int col = bn + ((j < 2) ? (tx * 4 + j * 2) : (64 + tx * 4 + (j - 2) * 2));
            if (col < N) {
                float2 v = upk(acc2[i][j]);
                *(float2*)&g_C[(size_t)row * N + col] = v;
                if (col >= 2560) {           // U columns: also write transposed copy
                    int b_ = row >> 11, s_ = row & (SS - 1);
                    int cc = col - 2560;
                    g_UT[(size_t)(((cc >> 4) * NB + b_) * NH + (cc & 15)) * SS + s_] = v.x;
                    int cc1 = cc + 1;
                    g_UT[(size_t)(((cc1 >> 4) * NB + b_) * NH + (cc1 & 15)) * SS + s_] = v.y;
                }
            }
        }
    }
}

// ---------------- attention via tf32 tensor-core mma --------------------------
// grid: (SS/128, NA*NB*NH) = (16, 128), 256 threads (8 warps).
// Warp w owns q-rows q0+16w..+15. Q tf32 fragments register-resident for the
// whole kernel. K tiles (128 keys x 64 d) staged transposed+tf32 into smem
// (pad 136 -> B-frag LDS conflict-free). Unshifted f32x2 softmax accumulation
// (scores O(10)), final 4-lane shfl reduce.
__global__ __launch_bounds__(256, 2) void attn_mma() {
    __shared__ unsigned Ks[DD][KPAD];   // 34.8 KB, tf32 bits, [d][key]
    __shared__ __align__(16) float Us[128];

    int tid = threadIdx.x;
    int warp = tid >> 5, lane = tid & 31;
    int gid = lane >> 2, tig = lane & 3;

    int abh = blockIdx.y;               // (a*NB + b)*NH + h
    int h = abh & 15;
    int ab = abh >> 4;
    int a = ab >> 2, b = ab & 3;
    int q0 = blockIdx.x * 128;

    int qcol = a * 1024 + h * DD;
    int kcol = 2048 + a * 256 + (h >> 2) * DD;
    const float* Cb = g_C + (size_t)b * SS * NTOT;
    const float* UT = g_UT + (size_t)abh * SS;

    // ---- Q fragments (tf32), scaled by 1/sqrt(64), all 8 k-steps ----
    unsigned qa[8][4];
    {
        const float* qr0 = Cb + (size_t)(q0 + 16 * warp + gid) * NTOT + qcol;
        const float* qr1 = qr0 + (size_t)8 * NTOT;
#pragma unroll
        for (int ks = 0; ks < 8; ks++) {
            int c0 = ks * 8 + tig;
            qa[ks][0] = tf32c(0.125f * qr0[c0]);
            qa[ks][1] = tf32c(0.125f * qr1[c0]);
            qa[ks][2] = tf32c(0.125f * qr0[c0 + 4]);
            qa[ks][3] = tf32c(0.125f * qr1[c0 + 4]);
        }
    }

    ull seA = 0ull, suA = 0ull, seB = 0ull, suB = 0ull;

    int kr = tid & 127, kh = tid >> 7;   // K loader: key row kr, d-half kh
    const float* kbase = Cb + (size_t)kr * NTOT + kcol + kh * 32;

    for (int kt = 0; kt < SS / 128; kt++) {
        __syncthreads();    // previous tile's Ks reads complete
        const float* src = kbase + (size_t)kt * 128 * NTOT;
#pragma unroll
        for (int j = 0; j < 8; j++) {
            float4 v = ((const float4*)src)[j];
            int d = kh * 32 + j * 4;
            Ks[d + 0][kr] = tf32c(v.x);
            Ks[d + 1][kr] = tf32c(v.y);
            Ks[d + 2][kr] = tf32c(v.z);
            Ks[d + 3][kr] = tf32c(v.w);
        }
        if (tid < 64)
            *(float2*)&Us[tid * 2] = *(const float2*)(UT + kt * 128 + tid * 2);
        __syncthreads();

#pragma unroll
        for (int nb = 0; nb < 16; nb++) {
            int n0 = nb * 8;
            float c0 = 0.f, c1 = 0.f, c2 = 0.f, c3 = 0.f;
#pragma unroll
            for (int ks = 0; ks < 8; ks++) {
                unsigned b0 = Ks[ks * 8 + tig][n0 + gid];
                unsigned b1 = Ks[ks * 8 + tig + 4][n0 + gid];
                mma_tf32(c0, c1, c2, c3,
                         qa[ks][0], qa[ks][1], qa[ks][2], qa[ks][3], b0, b1);
            }
            // rows: 16w+gid (c0,c1), 16w+8+gid (c2,c3); cols n0+2tig, n0+2tig+1
            float2 uu = *(const float2*)&Us[n0 + 2 * tig];
            ull u2 = pk(uu.x, uu.y);
            ull e0 = pexp(pk(c0, c1));
            ull e1 = pexp(pk(c2, c3));
            ADD2(seA, seA, e0); FMA2(suA, e0, u2, suA);
            ADD2(seB, seB, e1); FMA2(suB, e1, u2, suB);
        }
    }

    // ---- reduce over the 4 tig lanes of each quad ----
    float2 t;
    t = upk(seA); float seAs = t.x + t.y;
    t = upk(suA); float suAs = t.x + t.y;
    t = upk(seB); float seBs = t.x + t.y;
    t = upk(suB); float suBs = t.x + t.y;
#pragma unroll
    for (int m = 1; m < 4; m <<= 1) {
        seAs += __shfl_xor_sync(0xffffffffu, seAs, m);
        suAs += __shfl_xor_sync(0xffffffffu, suAs, m);
        seBs += __shfl_xor_sync(0xffffffffu, seBs, m);
        suBs += __shfl_xor_sync(0xffffffffu, suBs, m);
    }
    if (tig == 0) {
        int row = q0 + warp * 16 + gid;
        g_SH[(size_t)abh * SS + row]     = suAs / seAs;
        g_SH[(size_t)abh * SS + row + 8] = suBs / seBs;
    }
}

// ---------------- combine heads + sigmoid ------------------------------------
__global__ void combine_kernel() {
    int idx = blockIdx.x * blockDim.x + threadIdx.x;   // NA*NB*SS = 16384
    if (idx >= NA * NB * SS) return;
    int q = idx & (SS - 1);
    int ab = idx >> 11;
    float s = 0.f;
#pragma unroll
    for (int h = 0; h < NH; h++) s += g_SH[((size_t)ab * NH + h) * SS + q];
    g_SIG[idx] = 1.0f / (1.0f + expf(-s));
}

// ---------------- sizes (fp64 mean, fp32 final formula, C truncation) --------
__global__ void sizes_kernel(const float* __restrict__ scale_p) {
    int b = blockIdx.x;
    int tid = threadIdx.x;
    __shared__ double red[256];
    double s = 0.0;
    for (int q = tid; q < SS; q += 256) s += (double)g_SIG[b * SS + q];
    red[tid] = s;
    __syncthreads();
    for (int st = 128; st > 0; st >>= 1) {
        if (tid < st) red[tid] += red[tid + st];
        __syncthreads();
    }
    if (tid == 0) {
        float mean = (float)(red[0] / (double)SS);
        float val = mean * scale_p[0] * 8160.0f + 32.0f;
        g_sizes[b] = (int)val;
    }
}

// ---------------- segment weighted pooling + output --------------------------
__global__ __launch_bounds__(256) void pool_kernel(const float* __restrict__ x,
                                                   float* __restrict__ out,
                                                   int ml, int extras) {
    int b = blockIdx.y, j = blockIdx.x, tid = threadIdx.x;
    int sz = g_sizes[b];
    int off = ml - sz;
    float* orow = out + ((size_t)(b * ml + j)) * HID;
    int c = tid * 4;
    size_t maskbase = (size_t)NB * ml * HID;

    if (j < off) {
        *(float4*)&orow[c] = make_float4(0.f, 0.f, 0.f, 0.f);
        if (extras && tid == 0) out[maskbase + (size_t)b * ml + j] = 0.0f;
    } else {
        int s = j - off;
        double step = 2048.0 / (double)sz;
        int lo = (s == 0) ? 0 : (int)floor((double)s * step);
        int hi = (s + 1 == sz) ? SS : (int)floor((double)(s + 1) * step);
        float4 acc = make_float4(0.f, 0.f, 0.f, 0.f);
        float wsum = 0.f;
        const float* wv = g_SIG + (NA - 1) * NB * SS + b * SS;
        const float* xb = x + (size_t)b * SS * HID;
        for (int t = lo; t < hi; t++) {
            float w = wv[t];
            float4 xv = *(const float4*)&xb[(size_t)t * HID + c];
            acc.x = fmaf(xv.x, w, acc.x);
            acc.y = fmaf(xv.y, w, acc.y);
            acc.z = fmaf(xv.z, w, acc.z);
            acc.w = fmaf(xv.w, w, acc.w);
            wsum += w;
        }
        float den = wsum + 1e-8f;
        *(float4*)&orow[c] = make_float4(acc.x / den, acc.y / den, acc.z / den, acc.w / den);
        if (extras && tid == 0) out[maskbase + (size_t)b * ml + j] = 1.0f;
    }
    if (extras && j == 0 && tid == 0)
        out[maskbase + (size_t)NB * ml + b] = (float)sz;
}

// ---------------- host --------------------------------------------------------
extern "C" void kernel_launch(void* const* d_in, const int* in_sizes, int n_in,
                              void* d_out, int out_size) {
    const float* x    = (const float*)d_in[0];
    const float* Wq1  = (const float*)d_in[1];
    const float* Wk1  = (const float*)d_in[2];
    const float* Wv1  = (const float*)d_in[3];
    const float* Wo1  = (const float*)d_in[4];
    const float* Wq2  = (const float*)d_in[5];
    const float* Wk2  = (const float*)d_in[6];
    const float* Wv2  = (const float*)d_in[7];
    const float* Wo2  = (const float*)d_in[8];
    const float* scl  = (const float*)d_in[9];
    float* out = (float*)d_out;

    // derive max_len from out_size: out = B*ml*(HID+1) + B floats
    long long osz = (long long)out_size;
    int ml, extras;
    if (osz > NB && ((osz - NB) % (long long)(NB * (HID + 1))) == 0) {
        ml = (int)((osz - NB) / (NB * (HID + 1)));
        extras = 1;
    } else {
        ml = (int)(osz / (NB * HID));
        extras = 0;
    }
    if (ml < 1) ml = 1;

    pack_weights<<<dim3((NTOT + 255) / 256, HID), 256>>>(Wq1, Wk1, Wv1, Wo1,
                                                         Wq2, Wk2, Wv2, Wo2);
    gemm_fused<<<dim3((NTOT + 127) / 128, (NB * SS) / 128), 256>>>(x);
    attn_mma<<<dim3(SS / 128, NA * NB * NH), 256>>>();
    combine_kernel<<<(NA * NB * SS + 255) / 256, 256>>>();
    sizes_kernel<<<NB, 256>>>(scl);
    pool_kernel<<<dim3(ml, NB), 256>>>(x, out, ml, extras);
}

// round 17
// speedup vs baseline: 1.0873x; 1.0873x over previous
#include <cuda_runtime.h>
#include <cuda_bf16.h>
#include <math.h>

// Problem constants
#define NB 4          // batch
#define SS 2048       // seq len
#define HID 1024
#define NH 16         // heads
#define NKV 4
#define DD 64
#define NA 2          // two attentions
#define NTOT 2592     // 1024(Q1)+1024(Q2)+256(K1)+256(K2)+16(U1)+16(U2)
#define QT 128        // queries per CTA (attention)
#define KT 128        // keys per tile (attention)
#define KROW 132      // Ks smem row stride (words)

typedef unsigned long long ull;

// ---------------- scratch (device globals; no allocation allowed) ------------
__device__ float g_Bcat[HID * NTOT];        // concatenated weights [K][NTOT]
__device__ float g_C   [NB * SS * NTOT];    // projections (only Q cols used now)
__device__ float g_KT  [NA * NB * NKV * DD * SS]; // K pre-transposed [abkv][d][s]
__device__ float g_UT  [NA * NB * NH * SS]; // scalar-values transposed (a,b,h,s)
__device__ float g_SH  [NA * NB * NH * SS]; // per-head scalar attention out
__device__ float g_SIG [NA * NB * SS];      // sigmoid(score) per attn
__device__ int   g_sizes[NB];

// ---------------- f32x2 packed helpers ---------------------------------------
__device__ __forceinline__ ull pk(float lo, float hi) {
    ull r; asm("mov.b64 %0, {%1, %2};" : "=l"(r) : "f"(lo), "f"(hi)); return r;
}
__device__ __forceinline__ float2 upk(ull v) {
    float2 r; asm("mov.b64 {%0, %1}, %2;" : "=f"(r.x), "=f"(r.y) : "l"(v)); return r;
}
__device__ __forceinline__ void upki(ull v, int& a, int& b) {
    asm("mov.b64 {%0, %1}, %2;" : "=r"(a), "=r"(b) : "l"(v));
}
__device__ __forceinline__ ull pki(int lo, int hi) {
    ull r; asm("mov.b64 %0, {%1, %2};" : "=l"(r) : "r"(lo), "r"(hi)); return r;
}
#define FMA2(d, a, b, c) asm("fma.rn.f32x2 %0, %1, %2, %3;" : "=l"(d) : "l"(a), "l"(b), "l"(c))
#define MUL2(d, a, b)    asm("mul.rn.f32x2 %0, %1, %2;"     : "=l"(d) : "l"(a), "l"(b))
#define ADD2(d, a, b)    asm("add.rn.f32x2 %0, %1, %2;"     : "=l"(d) : "l"(a), "l"(b))

// packed exp (degree-5 2^f poly, exponent splice; valid for |s| < ~80)
__device__ __forceinline__ ull pexp(ull s2) {
    const ull C_L2E  = pk(1.4426950408889634f, 1.4426950408889634f);
    const ull C_MAG  = pk(12582912.0f, 12582912.0f);
    const ull C_NMAG = pk(-12582912.0f, -12582912.0f);
    const ull C_N1   = pk(-1.0f, -1.0f);
    const ull P5 = pk(1.3333558e-3f, 1.3333558e-3f);
    const ull P4 = pk(9.6181291e-3f, 9.6181291e-3f);
    const ull P3 = pk(5.5504109e-2f, 5.5504109e-2f);
    const ull P2 = pk(2.4022651e-1f, 2.4022651e-1f);
    const ull P1 = pk(6.9314718e-1f, 6.9314718e-1f);
    const ull P0 = pk(1.0f, 1.0f);
    ull y2; MUL2(y2, s2, C_L2E);
    ull t2; ADD2(t2, y2, C_MAG);
    ull n2; ADD2(n2, t2, C_NMAG);
    ull fr2; FMA2(fr2, n2, C_N1, y2);
    ull p2 = P5;
    FMA2(p2, p2, fr2, P4);
    FMA2(p2, p2, fr2, P3);
    FMA2(p2, p2, fr2, P2);
    FMA2(p2, p2, fr2, P1);
    FMA2(p2, p2, fr2, P0);
    int t0, t1; upki(t2, t0, t1);
    unsigned e0 = ((unsigned)t0 + 0xB4C0007Fu) << 23;   // (n+127)<<23
    unsigned e1 = ((unsigned)t1 + 0xB4C0007Fu) << 23;
    ull sc2 = pki((int)e0, (int)e1);
    ull r2; MUL2(r2, p2, sc2);
    return r2;
}

// cp.async helpers
#define CPA16(dst, src) \
    asm volatile("cp.async.cg.shared.global [%0], [%1], 16;" :: "r"(dst), "l"(src))
#define CPA_COMMIT()  asm volatile("cp.async.commit_group;" ::: "memory")
#define CPA_WAIT1()   asm volatile("cp.async.wait_group 1;" ::: "memory")
#define CPA_WAIT0()   asm volatile("cp.async.wait_group 0;" ::: "memory")

__device__ __forceinline__ unsigned su32(const void* p) {
    return (unsigned)__cvta_generic_to_shared(p);
}

// ---------------- weight packing: Bcat[k][c] ---------------------------------
__global__ void pack_weights(const float* __restrict__ Wq1, const float* __restrict__ Wk1,
                             const float* __restrict__ Wv1, const float* __restrict__ Wo1,
                             const float* __restrict__ Wq2, const float* __restrict__ Wk2,
                             const float* __restrict__ Wv2, const float* __restrict__ Wo2) {
    int c = blockIdx.x * 256 + threadIdx.x;
    int k = blockIdx.y;
    if (c >= NTOT) return;
    float v;
    if (c < 1024)      v = Wq1[(size_t)k * 1024 + c];
    else if (c < 2048) v = Wq2[(size_t)k * 1024 + (c - 1024)];
    else if (c < 2304) v = Wk1[(size_t)k * 256 + (c - 2048)];
    else if (c < 2560) v = Wk2[(size_t)k * 256 + (c - 2304)];
    else {
        int cc = c - 2560; int a = cc >> 4, h = cc & 15;
        const float* Wv = a ? Wv2 : Wv1;
        const float* Wo = a ? Wo2 : Wo1;
        int kv = h >> 2;
        float s = 0.f;
        const float* vr = Wv + (size_t)k * (NKV * DD) + kv * DD;
        const float* wr = Wo + h * DD;
#pragma unroll
        for (int d = 0; d < DD; d++) s = fmaf(vr[d], wr[d], s);
        v = s;
    }
    g_Bcat[(size_t)k * NTOT + c] = v;
}

// ---------------- fused projection GEMM: C = x @ Bcat --------------------------
// 128x128 tile, 8-k slabs, double-buffered smem, f32x2 microkernel.
// Epilogue routes: Q cols -> g_C, K cols -> g_KT (pre-transposed), U cols -> g_UT.
__global__ __launch_bounds__(256, 2) void gemm_fused(const float* __restrict__ A) {
    __shared__ __align__(16) float As[2][8][128];
    __shared__ __align__(16) float Bs[2][8][128];
    const int N = NTOT, K = HID;
    int tid = threadIdx.x;
    int bm = blockIdx.y * 128;
    int bn = blockIdx.x * 128;
    int ty = tid >> 4, tx = tid & 15;

    int arow = tid >> 1, acol = (tid & 1) * 4;
    int brow = tid >> 5, bcol = (tid & 31) * 4;
    int gn = bn + bcol;
    bool edge = (bn + 128 > N);

    ull acc2[8][4];
#pragma unroll
    for (int i = 0; i < 8; i++)
#pragma unroll
        for (int j = 0; j < 4; j++) acc2[i][j] = 0ull;

    const float* Aptr = A + (size_t)(bm + arow) * K + acol;
    const float* Bptr = g_Bcat + (size_t)brow * N + gn;

    float4 apre, bpre;
    apre = *(const float4*)(Aptr);
    if (!edge) bpre = *(const float4*)(Bptr);
    else {
        bpre.x = (gn + 0 < N) ? Bptr[0] : 0.f;
        bpre.y = (gn + 1 < N) ? Bptr[1] : 0.f;
        bpre.z = (gn + 2 < N) ? Bptr[2] : 0.f;
        bpre.w = (gn + 3 < N) ? Bptr[3] : 0.f;
    }
    As[0][acol + 0][arow] = apre.x;
    As[0][acol + 1][arow] = apre.y;
    As[0][acol + 2][arow] = apre.z;
    As[0][acol + 3][arow] = apre.w;
    *(float4*)&Bs[0][brow][bcol] = bpre;
    __syncthreads();

    for (int k0 = 0; k0 < K; k0 += 8) {
        int buf = (k0 >> 3) & 1;
        bool more = (k0 + 8 < K);

        if (more) {
            apre = *(const float4*)(Aptr + k0 + 8);
            const float* Bp = Bptr + (size_t)(k0 + 8) * N;
            if (!edge) bpre = *(const float4*)Bp;
            else {
                bpre.x = (gn + 0 < N) ? Bp[0] : 0.f;
                bpre.y = (gn + 1 < N) ? Bp[1] : 0.f;
                bpre.z = (gn + 2 < N) ? Bp[2] : 0.f;
                bpre.w = (gn + 3 < N) ? Bp[3] : 0.f;
            }
        }

#pragma unroll
        for (int kk = 0; kk < 8; kk++) {
            float4 a0 = *(const float4*)&As[buf][kk][ty * 4];
            float4 a1 = *(const float4*)&As[buf][kk][64 + ty * 4];
            ulonglong2 b0 = *(const ulonglong2*)&Bs[buf][kk][tx * 4];
            ulonglong2 b1 = *(const ulonglong2*)&Bs[buf][kk][64 + tx * 4];
            ull ap[8];
            ap[0] = pk(a0.x, a0.x); ap[1] = pk(a0.y, a0.y);
            ap[2] = pk(a0.z, a0.z); ap[3] = pk(a0.w, a0.w);
            ap[4] = pk(a1.x, a1.x); ap[5] = pk(a1.y, a1.y);
            ap[6] = pk(a1.z, a1.z); ap[7] = pk(a1.w, a1.w);
            ull bp[4] = {b0.x, b0.y, b1.x, b1.y};
#pragma unroll
            for (int i = 0; i < 8; i++)
#pragma unroll
                for (int j = 0; j < 4; j++) FMA2(acc2[i][j], ap[i], bp[j], acc2[i][j]);
        }

        if (more) {
            int nb = buf ^ 1;
            As[nb][acol + 0][arow] = apre.x;
            As[nb][acol + 1][arow] = apre.y;
            As[nb][acol + 2][arow] = apre.z;
            As[nb][acol + 3][arow] = apre.w;
            *(float4*)&Bs[nb][brow][bcol] = bpre;
            __syncthreads();
        }
    }

#pragma unroll
    for (int i = 0; i < 8; i++) {
        int row = bm + ((i < 4) ? (ty * 4 + i) : (64 + ty * 4 + i - 4));
#pragma unroll
        for (int j = 0; j < 4; j++) {
            int col = bn + ((j < 2) ? (tx * 4 + j * 2) : (64 + tx * 4 + (j - 2) * 2));
            if (col >= N) continue;
            float2 v = upk(acc2[i][j]);
            int b_ = row >> 11, s_ = row & (SS - 1);
            if (col < 2048) {
                *(float2*)&g_C[(size_t)row * NTOT + col] = v;   // Q columns
            } else if (col < 2560) {                            // K -> transposed
                int cc = col - 2048;
                int a0_ = cc >> 8, rr = cc & 255;
                int kv_ = rr >> 6, d_ = rr & 63;
                size_t kidx = ((size_t)((a0_ * NB + b_) * NKV + kv_) * DD + d_) * SS + s_;
                g_KT[kidx]      = v.x;
                g_KT[kidx + SS] = v.y;                          // d_+1 (pair in-range)
            } else {                                            // U -> transposed
                int cc = col - 2560;
                g_UT[(size_t)(((cc >> 4) * NB + b_) * NH + (cc & 15)) * SS + s_] = v.x;
                int cc1 = cc + 1;
                g_UT[(size_t)(((cc1 >> 4) * NB + b_) * NH + (cc1 & 15)) * SS + s_] = v.y;
            }
        }
    }
}

// ---------------- K tile cp.async issue ---------------------------------------
__device__ __forceinline__ void k_issue(unsigned ksb, const float* kg, int kt,
                                        int buf, int krow, int kc0) {
    unsigned dbase = ksb + (unsigned)(((buf * (DD * KROW)) + krow * KROW + kc0 * 4) * 4);
    const float* s = kg + (size_t)kt * KT + kc0 * 4;
#pragma unroll
    for (int j = 0; j < 8; j++)
        CPA16(dbase + j * 16, s + j * 4);
    CPA_COMMIT();
}

// ---------------- attention with scalar values --------------------------------
// grid: (SS/QT, NA*NB*NH) = (16,128), 256 threads. R8 math (unshifted f32x2
// softmax, 128q x 64k register tile done twice per 128-key smem tile).
// K streamed via cp.async double-buffer from pre-transposed g_KT (no prefetch
// registers). Dynamic smem: Qs[64][128] + Ks[2][64][132] = 100352 B.
__global__ __launch_bounds__(256, 2) void attn_kernel() {
    extern __shared__ __align__(16) float sm[];
    float (*Qs)[QT] = (float (*)[QT])sm;           // [64][128]
    float* Ksf = sm + DD * QT;                     // [2][64][132]

    int tid = threadIdx.x;
    int abh = blockIdx.y;               // (a*NB + b)*NH + h
    int h = abh & 15;
    int ab = abh >> 4;
    int a = ab >> 2, b = ab & 3;
    int q0 = blockIdx.x * QT;

    int qcol = a * 1024 + h * DD;
    const float* Cb = g_C + (size_t)b * SS * NTOT;
    const float* UT = g_UT + (size_t)abh * SS;
    int kv = h >> 2;

    // ---- load Q tile transposed + scaled by 1/sqrt(64) ----
    {
        int q = tid >> 1, half = tid & 1;
        const float* src = Cb + (size_t)(q0 + q) * NTOT + qcol + half * 32;
#pragma unroll
        for (int j = 0; j < 8; j++) {
            float4 v = ((const float4*)src)[j];
            int d = half * 32 + j * 4;
            Qs[d + 0][q] = v.x * 0.125f;
            Qs[d + 1][q] = v.y * 0.125f;
            Qs[d + 2][q] = v.z * 0.125f;
            Qs[d + 3][q] = v.w * 0.125f;
        }
    }

    // ---- cp.async K loader mapping: row = d (0..63), 8x16B chunks/thread ----
    int krow = tid >> 2;
    int kc0  = (tid & 3) * 8;
    unsigned ksb = su32(sm) + (unsigned)(DD * QT * 4);
    const float* kg = g_KT + ((size_t)(ab * NKV + kv) * DD + krow) * SS;

    k_issue(ksb, kg, 0, 0, krow, kc0);

    int ty = tid >> 4, tx = tid & 15;   // 16x16 grid: 8 q-rows x 4 keys each

    ull acc2[4][4];
    ull lsp[4], lap[4];
#pragma unroll
    for (int i = 0; i < 4; i++) { lsp[i] = 0ull; lap[i] = 0ull; }

    for (int kt = 0; kt < SS / KT; kt++) {
        int buf = kt & 1;
        if (kt + 1 < SS / KT) {
            k_issue(ksb, kg, kt + 1, buf ^ 1, krow, kc0);
            CPA_WAIT1();          // tile kt complete (1 group may stay in flight)
        } else {
            CPA_WAIT0();
        }
        __syncthreads();          // all threads' copies for tile kt visible

        const float* Kb = Ksf + buf * (DD * KROW);

#pragma unroll
        for (int h2 = 0; h2 < 2; h2++) {
#pragma unroll
            for (int i = 0; i < 4; i++)
#pragma unroll
                for (int j = 0; j < 4; j++) acc2[i][j] = 0ull;

#pragma unroll 16
            for (int d = 0; d < DD; d++) {
                ulonglong2 aq0 = *(const ulonglong2*)&Qs[d][ty * 8];
                ulonglong2 aq1 = *(const ulonglong2*)&Qs[d][ty * 8 + 4];
                float4 bv = *(const float4*)&Kb[d * KROW + h2 * 64 + tx * 4];
                ull b0 = pk(bv.x, bv.x), b1 = pk(bv.y, bv.y);
                ull b2 = pk(bv.z, bv.z), b3 = pk(bv.w, bv.w);
                ull ap[4] = {aq0.x, aq0.y, aq1.x, aq1.y};
#pragma unroll
                for (int i = 0; i < 4; i++) {
                    FMA2(acc2[i][0], ap[i], b0, acc2[i][0]);
                    FMA2(acc2[i][1], ap[i], b1, acc2[i][1]);
                    FMA2(acc2[i][2], ap[i], b2, acc2[i][2]);
                    FMA2(acc2[i][3], ap[i], b3, acc2[i][3]);
                }
            }

            const float4 u4 = *(const float4*)(UT + kt * KT + h2 * 64 + tx * 4);
            ull ud[4] = {pk(u4.x, u4.x), pk(u4.y, u4.y), pk(u4.z, u4.z), pk(u4.w, u4.w)};
#pragma unroll
            for (int i = 0; i < 4; i++) {
#pragma unroll
                for (int j = 0; j < 4; j++) {
                    ull e2 = pexp(acc2[i][j]);
                    ADD2(lsp[i], lsp[i], e2);
                    FMA2(lap[i], e2, ud[j], lap[i]);
                }
            }
        }
        __syncthreads();          // done reading buf before next issue into it
    }

    // ---- final reduce across the 16 tx lanes; rows ty*8 + rp*2 + {0,1} ----
#pragma unroll
    for (int rp = 0; rp < 4; rp++) {
        float2 lsv = upk(lsp[rp]);
        float2 lav = upk(lap[rp]);
        float v0 = lsv.x, v1 = lsv.y, w0 = lav.x, w1 = lav.y;
#pragma unroll
        for (int m = 1; m < 16; m <<= 1) {
            v0 += __shfl_xor_sync(0xffffffffu, v0, m);
            v1 += __shfl_xor_sync(0xffffffffu, v1, m);
            w0 += __shfl_xor_sync(0xffffffffu, w0, m);
            w1 += __shfl_xor_sync(0xffffffffu, w1, m);
        }
        if (tx == 0) {
            int row = q0 + ty * 8 + rp * 2;
            g_SH[(size_t)abh * SS + row + 0] = w0 / v0;
            g_SH[(size_t)abh * SS + row + 1] = w1 / v1;
        }
    }
}

// ---------------- combine heads + sigmoid ------------------------------------
__global__ void combine_kernel() {
    int idx = blockIdx.x * blockDim.x + threadIdx.x;   // NA*NB*SS = 16384
    if (idx >= NA * NB * SS) return;
    int q = idx & (SS - 1);
    int ab = idx >> 11;
    float s = 0.f;
#pragma unroll
    for (int h = 0; h < NH; h++) s += g_SH[((size_t)ab * NH + h) * SS + q];
    g_SIG[idx] = 1.0f / (1.0f + expf(-s));
}

// ---------------- sizes (fp64 mean, fp32 final formula, C truncation) --------
__global__ void sizes_kernel(const float* __restrict__ scale_p) {
    int b = blockIdx.x;
    int tid = threadIdx.x;
    __shared__ double red[256];
    double s = 0.0;
    for (int q = tid; q < SS; q += 256) s += (double)g_SIG[b * SS + q];
    red[tid] = s;
    __syncthreads();
    for (int st = 128; st > 0; st >>= 1) {
        if (tid < st) red[tid] += red[tid + st];
        __syncthreads();
    }
    if (tid == 0) {
        float mean = (float)(red[0] / (double)SS);
        float val = mean * scale_p[0] * 8160.0f + 32.0f;
        g_sizes[b] = (int)val;
    }
}

// ---------------- segment weighted pooling + output --------------------------
__global__ __launch_bounds__(256) void pool_kernel(const float* __restrict__ x,
                                                   float* __restrict__ out,
                                                   int ml, int extras) {
    int b = blockIdx.y, j = blockIdx.x, tid = threadIdx.x;
    int sz = g_sizes[b];
    int off = ml - sz;
    float* orow = out + ((size_t)(b * ml + j)) * HID;
    int c = tid * 4;
    size_t maskbase = (size_t)NB * ml * HID;

    if (j < off) {
        *(float4*)&orow[c] = make_float4(0.f, 0.f, 0.f, 0.f);
        if (extras && tid == 0) out[maskbase + (size_t)b * ml + j] = 0.0f;
    } else {
        int s = j - off;
        double step = 2048.0 / (double)sz;
        int lo = (s == 0) ? 0 : (int)floor((double)s * step);
        int hi = (s + 1 == sz) ? SS : (int)floor((double)(s + 1) * step);
        float4 acc = make_float4(0.f, 0.f, 0.f, 0.f);
        float wsum = 0.f;
        const float* wv = g_SIG + (NA - 1) * NB * SS + b * SS;
        const float* xb = x + (size_t)b * SS * HID;
        for (int t = lo; t < hi; t++) {
            float w = wv[t];
            float4 xv = *(const float4*)&xb[(size_t)t * HID + c];
            acc.x = fmaf(xv.x, w, acc.x);
            acc.y = fmaf(xv.y, w, acc.y);
            acc.z = fmaf(xv.z, w, acc.z);
            acc.w = fmaf(xv.w, w, acc.w);
            wsum += w;
        }
        float den = wsum + 1e-8f;
        *(float4*)&orow[c] = make_float4(acc.x / den, acc.y / den, acc.z / den, acc.w / den);
        if (extras && tid == 0) out[maskbase + (size_t)b * ml + j] = 1.0f;
    }
    if (extras && j == 0 && tid == 0)
        out[maskbase + (size_t)NB * ml + b] = (float)sz;
}

// ---------------- host --------------------------------------------------------
extern "C" void kernel_launch(void* const* d_in, const int* in_sizes, int n_in,
                              void* d_out, int out_size) {
    const float* x    = (const float*)d_in[0];
    const float* Wq1  = (const float*)d_in[1];
    const float* Wk1  = (const float*)d_in[2];
    const float* Wv1  = (const float*)d_in[3];
    const float* Wo1  = (const float*)d_in[4];
    const float* Wq2  = (const float*)d_in[5];
    const float* Wk2  = (const float*)d_in[6];
    const float* Wv2  = (const float*)d_in[7];
    const float* Wo2  = (const float*)d_in[8];
    const float* scl  = (const float*)d_in[9];
    float* out = (float*)d_out;

    // derive max_len from out_size: out = B*ml*(HID+1) + B floats
    long long osz = (long long)out_size;
    int ml, extras;
    if (osz > NB && ((osz - NB) % (long long)(NB * (HID + 1))) == 0) {
        ml = (int)((osz - NB) / (NB * (HID + 1)));
        extras = 1;
    } else {
        ml = (int)(osz / (NB * HID));
        extras = 0;
    }
    if (ml < 1) ml = 1;

    const int ATTN_SMEM = (DD * QT + 2 * DD * KROW) * (int)sizeof(float);  // 100352
    cudaFuncSetAttribute(attn_kernel, cudaFuncAttributeMaxDynamicSharedMemorySize,
                         ATTN_SMEM);

    pack_weights<<<dim3((NTOT + 255) / 256, HID), 256>>>(Wq1, Wk1, Wv1, Wo1,
                                                         Wq2, Wk2, Wv2, Wo2);
    gemm_fused<<<dim3((NTOT + 127) / 128, (NB * SS) / 128), 256>>>(x);
    attn_kernel<<<dim3(SS / QT, NA * NB * NH), 256, ATTN_SMEM>>>();
    combine_kernel<<<(NA * NB * SS + 255) / 256, 256>>>();
    sizes_kernel<<<NB, 256>>>(scl);
    pool_kernel<<<dim3(ml, NB), 256>>>(x, out, ml, extras);
}